// round 16
// baseline (speedup 1.0000x reference)
#include <cuda_runtime.h>
#include <cstdint>
#include <math.h>

// AttentionAggregator — heterogeneous CTA specialization: LDG-path blocks and
// TMA-path blocks co-resident on every SM. 14 rounds showed each gather path
// alone saturates at ~4TB/s for this pattern (L1tex MSHR cap vs TMA engine);
// R12's "dual path" serialized both inside one warp and proved nothing. Here
// the two paths run on independent warps: type = (bid/148)&1 so the two
// blocks co-scheduled per SM (wave-modular placement, period 148) are one of
// each. LDG blocks: R2's register-resident row path. TMA blocks: R10's bulk-
// copy path. Split 2368/1728 rows ~ the measured 4.4:3.7 rate ratio.
// features: [100000, 256] f32; nodes: [4096] i32; unique_ids: [16384] i32;
// neigh_idx: [4096, 10] i32. out: [4096, 256] f32.

#define N_NODES 4096
#define FDIM    256
#define NSAMP   10
#define ROW_BYTES 1024
#define WARP_SMEM (11 * ROW_BYTES)        // q + 10 embed rows
#define DATA_SMEM (8 * WARP_SMEM)         // 90112 B
#define SMEM_TOTAL (DATA_SMEM + 8 * 8)    // + 8 mbarriers

#define LDG_ROWS 2368                     // 296 blocks * 8 rows
#define GRID     512                      // 296 LDG + 216 TMA blocks

__device__ __forceinline__ void bulk_cp_1k(unsigned int dst, const void* src,
                                           unsigned int mbar) {
    asm volatile(
        "cp.async.bulk.shared::cta.global.mbarrier::complete_tx::bytes "
        "[%0], [%1], %2, [%3];"
        :: "r"(dst), "l"(src), "r"((unsigned)ROW_BYTES), "r"(mbar) : "memory");
}

__device__ __forceinline__ void mbar_wait_p0(unsigned int mbar) {
    unsigned int done;
    asm volatile(
        "{\n\t.reg .pred p;\n\t"
        "mbarrier.try_wait.parity.acquire.cta.shared::cta.b64 p, [%1], %2;\n\t"
        "selp.b32 %0, 1, 0, p;\n\t}"
        : "=r"(done) : "r"(mbar), "r"(0u) : "memory");
    if (!done) {
        asm volatile(
            "{\n\t.reg .pred P1;\n\t"
            "WL_%=:\n\t"
            "mbarrier.try_wait.parity.acquire.cta.shared::cta.b64 P1, [%0], %1, 0x989680;\n\t"
            "@P1 bra.uni WD_%=;\n\t"
            "bra.uni WL_%=;\n\t"
            "WD_%=:\n\t}"
            :: "r"(mbar), "r"(0u) : "memory");
    }
}

__device__ __forceinline__ void stcs128(float* p, float4 v) {
    asm volatile("st.global.cs.v4.f32 [%0], {%1,%2,%3,%4};"
                 :: "l"(p), "f"(v.x), "f"(v.y), "f"(v.z), "f"(v.w));
}

// shared index-resolve + dedup for one row (warp-uniform scalar loads)
__device__ __forceinline__ void resolve_row(const int* __restrict__ uids,
                                            const int* __restrict__ nidx,
                                            int row, int* uid, unsigned& dup)
{
    int cols[NSAMP];
    const int2* np = (const int2*)(nidx + (size_t)row * NSAMP);
    #pragma unroll
    for (int i = 0; i < 5; i++) {
        int2 v = np[i];
        cols[2*i+0] = v.x;
        cols[2*i+1] = v.y;
    }
    #pragma unroll
    for (int s = 0; s < NSAMP; s++)
        uid[s] = uids[cols[s]];
    dup = 0;
    #pragma unroll
    for (int s = 1; s < NSAMP; s++) {
        bool d = false;
        #pragma unroll
        for (int t = 0; t < NSAMP; t++)
            if (t < s) d |= (cols[t] == cols[s]);
        if (d) dup |= (1u << s);
    }
}

// softmax over distinct samples (weights left in dots[]), redundant per lane
__device__ __forceinline__ float softmax_w(float* dots, unsigned dup)
{
    float m = -INFINITY;
    #pragma unroll
    for (int s = 0; s < NSAMP; s++)
        if (!((dup >> s) & 1u)) m = fmaxf(m, dots[s]);
    float sum = 0.f;
    #pragma unroll
    for (int s = 0; s < NSAMP; s++) {
        float e = ((dup >> s) & 1u) ? 0.f : __expf(dots[s] - m);
        dots[s] = e;
        sum += e;
    }
    return 1.f / sum;
}

__global__ __launch_bounds__(256, 2)
void attn_agg_kernel(const float* __restrict__ feat,
                     const int*   __restrict__ nodes,
                     const int*   __restrict__ uids,
                     const int*   __restrict__ nidx,
                     float*       __restrict__ out)
{
    extern __shared__ char smem[];
    const int bid  = blockIdx.x;
    const int warp = threadIdx.x >> 5;
    const int lane = threadIdx.x & 31;

    // wave-modular placement has period 148: blocks co-resident on an SM
    // differ by 148 in bid -> alternate types by (bid/148)&1.
    const int phase = bid / 148;
    const bool is_ldg = !(phase & 1);

    if (is_ldg) {
        // ---------------- LDG path (R2): register-resident row ----------------
        const int ldg_idx = (phase == 0) ? bid : bid - 148;   // 0..295
        const int row = ldg_idx * 8 + warp;                    // 0..2367

        int uid[NSAMP]; unsigned dup;
        resolve_row(uids, nidx, row, uid, dup);
        const int node = nodes[row];

        const float4* qp = (const float4*)(feat + (size_t)node * FDIM);
        const float4 q0 = qp[lane];
        const float4 q1 = qp[lane + 32];

        float4 a0[NSAMP], a1[NSAMP];
        #pragma unroll
        for (int s = 0; s < NSAMP; s++) {
            const float4* ep = (const float4*)(feat + (size_t)uid[s] * FDIM);
            a0[s] = ep[lane];
            a1[s] = ep[lane + 32];
        }

        float dots[NSAMP];
        #pragma unroll
        for (int s = 0; s < NSAMP; s++) {
            float a = a0[s].x*q0.x + a0[s].y*q0.y + a0[s].z*q0.z + a0[s].w*q0.w
                    + a1[s].x*q1.x + a1[s].y*q1.y + a1[s].z*q1.z + a1[s].w*q1.w;
            #pragma unroll
            for (int o = 16; o; o >>= 1)
                a += __shfl_xor_sync(0xffffffffu, a, o);
            dots[s] = a;
        }

        const float inv = softmax_w(dots, dup);

        float4 o0 = make_float4(0.f,0.f,0.f,0.f);
        float4 o1 = make_float4(0.f,0.f,0.f,0.f);
        #pragma unroll
        for (int s = 0; s < NSAMP; s++) {
            const float ws = dots[s] * inv;
            o0.x += ws*a0[s].x; o0.y += ws*a0[s].y;
            o0.z += ws*a0[s].z; o0.w += ws*a0[s].w;
            o1.x += ws*a1[s].x; o1.y += ws*a1[s].y;
            o1.z += ws*a1[s].z; o1.w += ws*a1[s].w;
        }
        float* op = out + (size_t)row * FDIM;
        stcs128(op + lane * 4, o0);
        stcs128(op + (lane + 32) * 4, o1);
    } else {
        // ---------------- TMA path (R10): bulk-copy row into SMEM -------------
        const int tma_idx = (phase == 1) ? bid - 148 : 148 + (bid - 444);
        const int row = LDG_ROWS + tma_idx * 8 + warp;         // 2368..4095

        char* wdata = smem + warp * WARP_SMEM;
        const unsigned int sdata = (unsigned int)__cvta_generic_to_shared(wdata);
        const unsigned int smbar =
            (unsigned int)__cvta_generic_to_shared(smem + DATA_SMEM + warp * 8);

        int uid[NSAMP]; unsigned dup;
        resolve_row(uids, nidx, row, uid, dup);
        const int node = nodes[row];

        if (lane == 0) {
            asm volatile("mbarrier.init.shared.b64 [%0], %1;"
                         :: "r"(smbar), "r"(1) : "memory");
        }
        __syncwarp();
        if (lane == 0) {
            asm volatile("mbarrier.arrive.expect_tx.shared.b64 _, [%0], %1;"
                         :: "r"(smbar), "r"((unsigned)WARP_SMEM) : "memory");
            bulk_cp_1k(sdata, feat + (size_t)node * FDIM, smbar);
            #pragma unroll
            for (int s = 0; s < NSAMP; s++)
                bulk_cp_1k(sdata + (unsigned)(1 + s) * ROW_BYTES,
                           feat + (size_t)uid[s] * FDIM, smbar);
        }

        mbar_wait_p0(smbar);

        const float4* qf = (const float4*)wdata;
        const float4 q0 = qf[lane];
        const float4 q1 = qf[lane + 32];

        float dots[NSAMP];
        #pragma unroll
        for (int s = 0; s < NSAMP; s++) {
            const float4* ep = (const float4*)(wdata + (1 + s) * ROW_BYTES);
            const float4 b0 = ep[lane];
            const float4 b1 = ep[lane + 32];
            float a = b0.x*q0.x + b0.y*q0.y + b0.z*q0.z + b0.w*q0.w
                    + b1.x*q1.x + b1.y*q1.y + b1.z*q1.z + b1.w*q1.w;
            #pragma unroll
            for (int o = 16; o; o >>= 1)
                a += __shfl_xor_sync(0xffffffffu, a, o);
            dots[s] = a;
        }

        const float inv = softmax_w(dots, dup);

        float4 o0 = make_float4(0.f,0.f,0.f,0.f);
        float4 o1 = make_float4(0.f,0.f,0.f,0.f);
        #pragma unroll
        for (int s = 0; s < NSAMP; s++) {
            const float ws = dots[s] * inv;
            const float4* ep = (const float4*)(wdata + (1 + s) * ROW_BYTES);
            const float4 b0 = ep[lane];
            const float4 b1 = ep[lane + 32];
            o0.x += ws*b0.x; o0.y += ws*b0.y;
            o0.z += ws*b0.z; o0.w += ws*b0.w;
            o1.x += ws*b1.x; o1.y += ws*b1.y;
            o1.z += ws*b1.z; o1.w += ws*b1.w;
        }
        float* op = out + (size_t)row * FDIM;
        stcs128(op + lane * 4, o0);
        stcs128(op + (lane + 32) * 4, o1);
    }
}

extern "C" void kernel_launch(void* const* d_in, const int* in_sizes, int n_in,
                              void* d_out, int out_size)
{
    const float* feat  = (const float*)d_in[0];
    const int*   nodes = (const int*)  d_in[1];
    const int*   uids  = (const int*)  d_in[2];
    const int*   nidx  = (const int*)  d_in[3];
    float*       out   = (float*)d_out;
    (void)in_sizes; (void)n_in; (void)out_size;

    cudaFuncSetAttribute(attn_agg_kernel,
                         cudaFuncAttributeMaxDynamicSharedMemorySize,
                         SMEM_TOTAL);
    attn_agg_kernel<<<GRID, 256, SMEM_TOTAL>>>(feat, nodes, uids, nidx, out);
}

// round 17
// speedup vs baseline: 1.0787x; 1.0787x over previous
#include <cuda_runtime.h>
#include <cstdint>
#include <math.h>

// AttentionAggregator — FINAL. Champion shape (R7): 2 rows/warp, row A
// register-resident (22 independent LDG.128), row B staged to SMEM via
// cp.async (second in-flight reservoir, zero held registers), 4 warps/block,
// plus R9's streaming output stores (output never re-read).
//
// Session finding: nine structurally distinct gather schemes (LDG/cp.async/
// TMA/pipelined-TMA/dual-path/CTA-specialized/two-kernel/evict_last) all
// converge on ~4.2TB/s effective for random 1KB row gathers on sm_103a — a
// shared SM->LTS scattered-request limit. 41MB of irreducible fp32 gathers
// => ~10.2us kernel floor; this kernel sits on it.
// features: [100000, 256] f32; nodes: [4096] i32; unique_ids: [16384] i32;
// neigh_idx: [4096, 10] i32. out: [4096, 256] f32.

#define N_NODES 4096
#define FDIM    256
#define NSAMP   10
#define WARPS_PER_BLOCK 4
#define ROWS_PER_BLOCK  (WARPS_PER_BLOCK * 2)
#define SM_ROW_F4 64                      // 256 floats = 64 float4 per row
#define SM_WARP_F4 ((1 + NSAMP) * SM_ROW_F4)   // q_B + 10 embed rows

__device__ __forceinline__ void cp_async16(unsigned int dst, const void* src) {
    asm volatile("cp.async.cg.shared.global [%0], [%1], 16;"
                 :: "r"(dst), "l"(src));
}

__device__ __forceinline__ void stcs128(float* p, float4 v) {
    asm volatile("st.global.cs.v4.f32 [%0], {%1,%2,%3,%4};"
                 :: "l"(p), "f"(v.x), "f"(v.y), "f"(v.z), "f"(v.w));
}

__global__ __launch_bounds__(WARPS_PER_BLOCK * 32)
void attn_agg_kernel(const float* __restrict__ feat,
                     const int*   __restrict__ nodes,
                     const int*   __restrict__ uids,
                     const int*   __restrict__ nidx,
                     float*       __restrict__ out)
{
    const int warp = threadIdx.x >> 5;
    const int lane = threadIdx.x & 31;
    const int row0 = (blockIdx.x * WARPS_PER_BLOCK + warp) * 2;  // A=row0, B=row0+1

    __shared__ float4 sbuf[WARPS_PER_BLOCK][SM_WARP_F4];   // 45056 B
    float4* wbuf = sbuf[warp];
    const unsigned int sbase = (unsigned int)__cvta_generic_to_shared(wbuf);

    // --- indices for BOTH rows, issued together (80B contiguous nidx) ---
    int cols[2 * NSAMP];
    {
        const int4* np = (const int4*)(nidx + (size_t)row0 * NSAMP);
        #pragma unroll
        for (int i = 0; i < 5; i++) {
            int4 v = np[i];
            cols[4*i+0] = v.x; cols[4*i+1] = v.y;
            cols[4*i+2] = v.z; cols[4*i+3] = v.w;
        }
    }
    int uid[2 * NSAMP];
    #pragma unroll
    for (int s = 0; s < 2 * NSAMP; s++)
        uid[s] = uids[cols[s]];

    // Per-row duplicate-column masks (dense mask counts repeated cols once).
    unsigned dup[2] = {0u, 0u};
    #pragma unroll
    for (int r = 0; r < 2; r++)
        #pragma unroll
        for (int s = 1; s < NSAMP; s++) {
            bool d = false;
            #pragma unroll
            for (int t = 0; t < NSAMP; t++)
                if (t < s) d |= (cols[r*NSAMP+t] == cols[r*NSAMP+s]);
            if (d) dup[r] |= (1u << s);
        }

    const int2 nn = *(const int2*)(nodes + row0);

    // --- fire row B into SMEM: 22 cp.async per lane, zero regs held ---
    {
        const float* qB = feat + (size_t)nn.y * FDIM;
        cp_async16(sbase + (unsigned int)lane * 16u,        qB + lane * 4);
        cp_async16(sbase + (unsigned int)(lane + 32) * 16u, qB + (lane + 32) * 4);
        #pragma unroll
        for (int s = 0; s < NSAMP; s++) {
            const float* eB = feat + (size_t)uid[NSAMP + s] * FDIM;
            const unsigned int off = sbase + (unsigned int)(1 + s) * 1024u;
            cp_async16(off + (unsigned int)lane * 16u,        eB + lane * 4);
            cp_async16(off + (unsigned int)(lane + 32) * 16u, eB + (lane + 32) * 4);
        }
        asm volatile("cp.async.commit_group;" ::: "memory");
    }

    // --- row A: register-resident (22 independent LDG.128) ---
    const float4* qpA = (const float4*)(feat + (size_t)nn.x * FDIM);
    const float4 qA0 = qpA[lane];
    const float4 qA1 = qpA[lane + 32];

    float4 a0[NSAMP], a1[NSAMP];
    #pragma unroll
    for (int s = 0; s < NSAMP; s++) {
        const float4* ep = (const float4*)(feat + (size_t)uid[s] * FDIM);
        a0[s] = ep[lane];
        a1[s] = ep[lane + 32];
    }

    float dots[NSAMP];
    #pragma unroll
    for (int s = 0; s < NSAMP; s++) {
        float a = a0[s].x*qA0.x + a0[s].y*qA0.y + a0[s].z*qA0.z + a0[s].w*qA0.w
                + a1[s].x*qA1.x + a1[s].y*qA1.y + a1[s].z*qA1.z + a1[s].w*qA1.w;
        #pragma unroll
        for (int o = 16; o; o >>= 1)
            a += __shfl_xor_sync(0xffffffffu, a, o);
        dots[s] = a;
    }

    // softmax A (redundant per lane) + aggregate + streaming store
    {
        float m = -INFINITY;
        #pragma unroll
        for (int s = 0; s < NSAMP; s++)
            if (!((dup[0] >> s) & 1u)) m = fmaxf(m, dots[s]);
        float sum = 0.f;
        #pragma unroll
        for (int s = 0; s < NSAMP; s++) {
            float e = ((dup[0] >> s) & 1u) ? 0.f : __expf(dots[s] - m);
            dots[s] = e; sum += e;
        }
        const float inv = 1.f / sum;

        float4 o0 = make_float4(0.f,0.f,0.f,0.f);
        float4 o1 = make_float4(0.f,0.f,0.f,0.f);
        #pragma unroll
        for (int s = 0; s < NSAMP; s++) {
            const float ws = dots[s] * inv;
            o0.x += ws*a0[s].x; o0.y += ws*a0[s].y;
            o0.z += ws*a0[s].z; o0.w += ws*a0[s].w;
            o1.x += ws*a1[s].x; o1.y += ws*a1[s].y;
            o1.z += ws*a1[s].z; o1.w += ws*a1[s].w;
        }
        float* op = out + (size_t)row0 * FDIM;
        stcs128(op + lane * 4, o0);
        stcs128(op + (lane + 32) * 4, o1);
    }

    // --- row B: compute from SMEM (each lane reads back its own copies) ---
    asm volatile("cp.async.wait_group 0;" ::: "memory");
    __syncwarp();

    const float4 qB0 = wbuf[lane];
    const float4 qB1 = wbuf[lane + 32];

    #pragma unroll
    for (int s = 0; s < NSAMP; s++) {
        const float4 b0 = wbuf[(1 + s) * SM_ROW_F4 + lane];
        const float4 b1 = wbuf[(1 + s) * SM_ROW_F4 + lane + 32];
        float a = b0.x*qB0.x + b0.y*qB0.y + b0.z*qB0.z + b0.w*qB0.w
                + b1.x*qB1.x + b1.y*qB1.y + b1.z*qB1.z + b1.w*qB1.w;
        #pragma unroll
        for (int o = 16; o; o >>= 1)
            a += __shfl_xor_sync(0xffffffffu, a, o);
        dots[s] = a;
    }

    {
        float m = -INFINITY;
        #pragma unroll
        for (int s = 0; s < NSAMP; s++)
            if (!((dup[1] >> s) & 1u)) m = fmaxf(m, dots[s]);
        float sum = 0.f;
        #pragma unroll
        for (int s = 0; s < NSAMP; s++) {
            float e = ((dup[1] >> s) & 1u) ? 0.f : __expf(dots[s] - m);
            dots[s] = e; sum += e;
        }
        const float inv = 1.f / sum;

        float4 o0 = make_float4(0.f,0.f,0.f,0.f);
        float4 o1 = make_float4(0.f,0.f,0.f,0.f);
        #pragma unroll
        for (int s = 0; s < NSAMP; s++) {
            const float ws = dots[s] * inv;
            const float4 b0 = wbuf[(1 + s) * SM_ROW_F4 + lane];
            const float4 b1 = wbuf[(1 + s) * SM_ROW_F4 + lane + 32];
            o0.x += ws*b0.x; o0.y += ws*b0.y;
            o0.z += ws*b0.z; o0.w += ws*b0.w;
            o1.x += ws*b1.x; o1.y += ws*b1.y;
            o1.z += ws*b1.z; o1.w += ws*b1.w;
        }
        float* op = out + (size_t)(row0 + 1) * FDIM;
        stcs128(op + lane * 4, o0);
        stcs128(op + (lane + 32) * 4, o1);
    }
}

extern "C" void kernel_launch(void* const* d_in, const int* in_sizes, int n_in,
                              void* d_out, int out_size)
{
    const float* feat  = (const float*)d_in[0];
    const int*   nodes = (const int*)  d_in[1];
    const int*   uids  = (const int*)  d_in[2];
    const int*   nidx  = (const int*)  d_in[3];
    float*       out   = (float*)d_out;
    (void)in_sizes; (void)n_in; (void)out_size;

    attn_agg_kernel<<<N_NODES / ROWS_PER_BLOCK, WARPS_PER_BLOCK * 32>>>(
        feat, nodes, uids, nidx, out);
}